// round 7
// baseline (speedup 1.0000x reference)
#include <cuda_runtime.h>
#include <cstdio>
#include <cstdint>

// ---------------------------------------------------------------------------
// Batched greedy nearest-neighbor (B=64, N=1000), latency-chain optimized.
//
// Stage 1 (prefetch kernel, ~25us): the chain will read exactly the rows of
// {start} U {initially-unmasked nodes} -- computable upfront. Prefetch all
// their cache lines into L2 (~128MB ~ L2 capacity) at full DRAM bandwidth.
//
// Stage 2 (chain kernel): one 128-thread CTA per batch; 2 float4 slots per
// thread; per step 2x asm ld.global.nc.v4.f32 (order-guaranteed, now mostly
// L2 hits), 8-elem local argmin, REDUX min(value)+min(col), 4-warp combine
// via double-buffered smem with ONE __syncthreads per step.
// Active-step count C = popcount(~mask0); tail is pad fill. Output = f32.
// ---------------------------------------------------------------------------

#define MK_BYTE  0   // u8 bool
#define MK_WORD  1   // i32 / f32 (word != 0 is truth)
#define MK_DWORD 2   // i64 (low word at stride 2)
#define MK_HALF  3   // u16 / bf16 / f16

#define SK_I32 0
#define SK_I64 1
#define SK_F32 2

#define PF_CTAS_PER_BATCH 4

__device__ int g_mask_kind, g_start_kind, g_pad;

__global__ void detect_kernel(const unsigned int* __restrict__ mw, int m_nwords,
                              const unsigned int* __restrict__ sw, int s_nwords,
                              const unsigned int* __restrict__ pw, int has_pad,
                              int N)
{
    __shared__ int vi_word, vi_dword, vi_half, s_odd_nz, s_small_int, s_nonfloat;
    if (threadIdx.x == 0) {
        vi_word = 0; vi_dword = 0; vi_half = 0;
        s_odd_nz = 0; s_small_int = 0; s_nonfloat = 0;
    }
    __syncthreads();

    int a = 0, b = 0, c = 0;
    for (int i = threadIdx.x; i < m_nwords; i += blockDim.x) {
        unsigned int v = mw[i];
        if (v != 0u && v != 1u && v != 0x3F800000u) a = 1;
        if ((i & 1) ? (v != 0u) : (v > 1u)) b = 1;
        unsigned int h0 = v & 0xFFFFu, h1 = v >> 16;
        if (!(h0 == 0u || h0 == 1u || h0 == 0x3F80u || h0 == 0x3C00u)) c = 1;
        if (!(h1 == 0u || h1 == 1u || h1 == 0x3F80u || h1 == 0x3C00u)) c = 1;
    }
    if (a) vi_word = 1;
    if (b) vi_dword = 1;
    if (c) vi_half = 1;

    int o = 0, si = 0, nf = 0;
    for (int i = threadIdx.x; i < s_nwords; i += blockDim.x) {
        unsigned int v = sw[i];
        if ((i & 1) && v != 0u) o = 1;
        if (v >= 1u && v < 0x01000000u) si = 1;
        if (!(v == 0u || (v >= 0x30000000u && v < 0x45000000u))) nf = 1;
    }
    if (o)  s_odd_nz = 1;
    if (si) s_small_int = 1;
    if (nf) s_nonfloat = 1;
    __syncthreads();

    if (threadIdx.x == 0) {
        int mk;
        if      (!vi_word)  mk = MK_WORD;
        else if (!vi_dword) mk = MK_DWORD;
        else if (!vi_half)  mk = MK_HALF;
        else                mk = MK_BYTE;
        g_mask_kind = mk;

        int sk;
        if      (!s_odd_nz && s_nwords >= 2)  sk = SK_I64;
        else if (!s_nonfloat && !s_small_int) sk = SK_F32;
        else                                  sk = SK_I32;
        g_start_kind = sk;

        int pad = N;
        if (has_pad) {
            unsigned int p0 = pw[0];
            if (p0 < 0x01000000u) {
                pad = (int)p0;
                if (p0 == 0u) {
                    unsigned int p1 = pw[1];
                    if (p1 >= 0x3FF00000u && p1 < 0x42000000u)
                        pad = (int)__hiloint2double((int)p1, 0);
                }
            } else {
                float f = __uint_as_float(p0);
                if (f >= 0.0f && f < 16777216.0f) pad = (int)f;
            }
        }
        g_pad = pad;
    }
}

__device__ __forceinline__ bool mask_at(const void* mask, int mk, int off) {
    if (mk == MK_WORD)  return ((const unsigned int*)mask)[off]      != 0u;
    if (mk == MK_BYTE)  return ((const unsigned char*)mask)[off]     != 0u;
    if (mk == MK_HALF)  return ((const unsigned short*)mask)[off]    != 0u;
    return ((const unsigned int*)mask)[2 * off] != 0u;                 // i64
}

__device__ __forceinline__ int read_start(const void* start_idx, int sk, int b) {
    const int* s32 = (const int*)start_idx;
    if (sk == SK_I64) return s32[2 * b];
    if (sk == SK_F32) return (int)((const float*)start_idx)[b];
    return s32[b];
}

// Prefetch every 128B line overlapping [p, p + nbytes), staying in-bounds.
__device__ __forceinline__ void prefetch_row(const char* p, int nbytes,
                                             int t0, int tstride)
{
    uintptr_t first = (uintptr_t)p & ~(uintptr_t)127;           // aligned down
    uintptr_t last  = ((uintptr_t)p + nbytes - 1) & ~(uintptr_t)127;
    int nlines = (int)((last - first) >> 7) + 1;
    for (int i = t0; i < nlines; i += tstride) {
        const char* q = (const char*)(first + ((uintptr_t)i << 7));
        asm volatile("prefetch.global.L2 [%0];" :: "l"(q));
    }
}

// ---- Stage 1: warm L2 with every row the chain can touch ------------------
__global__ __launch_bounds__(256)
void prefetch_kernel(const float* __restrict__ dist,
                     const void*  __restrict__ mask,
                     const void*  __restrict__ start_idx,
                     int B, int N)
{
    const int b   = blockIdx.x / PF_CTAS_PER_BATCH;
    const int q   = blockIdx.x % PF_CTAS_PER_BATCH;
    const int tid = threadIdx.x;
    const int mk  = g_mask_kind;
    const int row_bytes = 4 * N;
    const char* dbase = (const char*)(dist + (size_t)b * N * N);

    // start row (may be masked): CTA q==0 covers it cooperatively
    if (q == 0) {
        int point = read_start(start_idx, g_start_kind, b);
        if (point < 0) point = 0;
        if (point >= N) point = N - 1;
        prefetch_row(dbase + (size_t)point * row_bytes, row_bytes, tid, 256);
    }

    const int per = (N + PF_CTAS_PER_BATCH - 1) / PF_CTAS_PER_BATCH;
    const int lo = q * per;
    const int hi = (lo + per < N) ? lo + per : N;
    for (int col = lo + tid; col < hi; col += blockDim.x) {
        if (!mask_at(mask, mk, b * N + col))         // unmasked -> will be read
            prefetch_row(dbase + (size_t)col * row_bytes, row_bytes, 0, 1);
    }
}

__device__ __forceinline__ float4 ldg128_nc(const float* p) {
    float4 v;
    asm volatile("ld.global.nc.v4.f32 {%0,%1,%2,%3}, [%4];"
                 : "=f"(v.x), "=f"(v.y), "=f"(v.z), "=f"(v.w)
                 : "l"(p));
    return v;
}

// ---- Stage 2: the greedy chain --------------------------------------------
__global__ __launch_bounds__(128, 1)
void greedy_nn_kernel(const float* __restrict__ dist,
                      const void*  __restrict__ mask,
                      const void*  __restrict__ start_idx,
                      float*       __restrict__ out,
                      int B, int N, int write_len)
{
    __shared__ unsigned long long sbuf[2][4];
    __shared__ int scnt[4];

    const int b    = blockIdx.x;
    const int tid  = threadIdx.x;
    const int lane = tid & 31;
    const int wid  = tid >> 5;
    const int mk   = g_mask_kind;
    const float padf = (float)g_pad;
    const int nf4  = N >> 2;                       // full float4s per row
    const unsigned int BIGBITS = 0x49742400u;      // bits of 1.0e6f

    const bool v0 = (tid       < nf4);
    const bool v1 = (tid + 128 < nf4);

    // ---- visited bits: slot s, r -> col 4*(tid+128s)+r, bit s*4+r ---------
    unsigned int m = 0;
    #pragma unroll
    for (int s = 0; s < 2; s++) {
        #pragma unroll
        for (int r = 0; r < 4; r++) {
            int col = 4 * (tid + 128 * s) + r;
            bool mb = true;                        // out-of-range -> visited
            if (col < N) mb = mask_at(mask, mk, b * N + col);
            if (mb) m |= 1u << (s * 4 + r);
        }
    }

    // ---- active step count C = # initially-unvisited nodes ----------------
    {
        unsigned int cnt = 8u - (unsigned)__popc(m);
        cnt = __reduce_add_sync(0xffffffffu, cnt);
        if (lane == 0) scnt[wid] = (int)cnt;
    }
    __syncthreads();
    const int C = scnt[0] + scnt[1] + scnt[2] + scnt[3];

    int point = read_start(start_idx, g_start_kind, b);
    if (point < 0) point = 0;
    if (point >= N) point = N - 1;

    const float* dbase = dist + (size_t)b * N * N;
    float* pred = out + (size_t)b * N;

    for (int t = 0; t < C; t++) {
        const float* rp = dbase + (size_t)point * N;

        float4 a = v0 ? ldg128_nc(rp + 4 * tid)
                      : make_float4(1e6f, 1e6f, 1e6f, 1e6f);
        float4 c = v1 ? ldg128_nc(rp + 4 * (tid + 128))
                      : make_float4(1e6f, 1e6f, 1e6f, 1e6f);

        // local argmin over 8 elems (ascending col => strict '<' keeps lowest)
        unsigned int bb = BIGBITS, bc = 0;
        const float* pa = (const float*)&a;
        const float* pc = (const float*)&c;
        #pragma unroll
        for (int r = 0; r < 4; r++) {
            unsigned int fb = ((m >> r) & 1u) ? BIGBITS : __float_as_uint(pa[r]);
            if (fb < bb) { bb = fb; bc = 4 * tid + r; }
        }
        #pragma unroll
        for (int r = 0; r < 4; r++) {
            unsigned int fb = ((m >> (4 + r)) & 1u) ? BIGBITS : __float_as_uint(pc[r]);
            if (fb < bb) { bb = fb; bc = 4 * (tid + 128) + r; }
        }

        unsigned int wmin = __reduce_min_sync(0xffffffffu, bb);
        unsigned int colc = (bb == wmin) ? bc : 0xFFFFFFFFu;
        unsigned int wcol = __reduce_min_sync(0xffffffffu, colc);

        if (lane == 0)
            sbuf[t & 1][wid] = ((unsigned long long)wmin << 32) | wcol;
        __syncthreads();
        unsigned long long k0 = sbuf[t & 1][0], k1 = sbuf[t & 1][1];
        unsigned long long k2 = sbuf[t & 1][2], k3 = sbuf[t & 1][3];
        unsigned long long ka = k0 < k1 ? k0 : k1;
        unsigned long long kb = k2 < k3 ? k2 : k3;
        unsigned long long k  = ka < kb ? ka : kb;

        int idx = (int)(unsigned int)k;
        if (tid == 0) pred[t] = (float)idx;

        int f = idx >> 2;
        if ((f & 127) == tid)
            m |= 1u << (((f >> 7) << 2) | (idx & 3));
        point = idx;
    }

    for (int t = C + tid; t < N; t += 128) pred[t] = padf;
    if (write_len && tid == 0) out[(size_t)B * N + b] = (float)C;
}

extern "C" void kernel_launch(void* const* d_in, const int* in_sizes, int n_in,
                              void* d_out, int out_size)
{
    // ---- identify inputs by element count (order-proof) -------------------
    int di = 0, mi = -1, si = -1, pi = -1;
    for (int i = 1; i < n_in; i++)
        if (in_sizes[i] > in_sizes[di]) di = i;            // distance: largest
    for (int i = 0; i < n_in; i++) {
        if (i == di) continue;
        if (pi < 0 || in_sizes[i] < in_sizes[pi]) pi = i;  // pad: smallest
    }
    for (int i = 0; i < n_in; i++) {
        if (i == di || i == pi) continue;
        if (mi < 0) { mi = i; continue; }
        si = i;
    }
    if (si >= 0 && in_sizes[si] > in_sizes[mi]) { int t = mi; mi = si; si = t; }
    if (si < 0) { si = pi; pi = -1; }                      // only 3 inputs

    const float* dist  = (const float*)d_in[di];
    const void*  mask  = d_in[mi];
    const void*  start = d_in[si];
    const void*  padp  = (pi >= 0) ? d_in[pi] : nullptr;

    const int B = in_sizes[si];
    const int N = in_sizes[mi] / B;

    int m_nwords = in_sizes[mi] / 4;
    int s_nwords = in_sizes[si];
    detect_kernel<<<1, 256>>>((const unsigned int*)mask, m_nwords,
                              (const unsigned int*)start, s_nwords,
                              padp ? (const unsigned int*)padp
                                   : (const unsigned int*)start,
                              padp ? 1 : 0, N);

    prefetch_kernel<<<B * PF_CTAS_PER_BATCH, 256>>>(dist, mask, start, B, N);

    int write_len = (out_size >= B * N + B) ? 1 : 0;
    greedy_nn_kernel<<<B, 128>>>(dist, mask, start, (float*)d_out,
                                 B, N, write_len);
}